// round 1
// baseline (speedup 1.0000x reference)
#include <cuda_runtime.h>
#include <math.h>

#define S_LEN 2048
#define B_SZ  64
#define XDIM  64
#define DXD   128
#define HDIM  256
#define DHD   128
#define ODIM  64

// Scratch (alloc-free rule: __device__ globals)
__device__ float g_U[S_LEN * B_SZ * HDIM];   // U[t,b,:] = feat @ Wih^T + bih + bhh
__device__ float g_Hs[S_LEN * B_SZ * HDIM];  // hidden state ENTERING step t (h_0 = 0)

// ---------------------------------------------------------------------------
// Kernel A: fused feature extractor + input projection
//   feat = tanh(x @ Wx + bx)            [rows, 128]
//   U    = feat @ Wih^T + (bih + bhh)   [rows, 256]
// Weights cached in smem; 16-row tiles; 4x4 register blocking (FMA-bound).
// ---------------------------------------------------------------------------
__global__ __launch_bounds__(256, 1) void kA(
    const float* __restrict__ x,
    const float* __restrict__ Wx, const float* __restrict__ bx,
    const float* __restrict__ Wih, const float* __restrict__ bih,
    const float* __restrict__ bhh)
{
    extern __shared__ float sm[];
    float* sWx   = sm;                    // [64][128]
    float* sWihT = sWx + 64 * 128;        // [128][260]  (WihT[j][i] = Wih[i][j], pad 260)
    float* sbx   = sWihT + 128 * 260;     // [128]
    float* sbU   = sbx + 128;             // [256]
    float* sx    = sbU + 256;             // [16][64]
    float* sfeat = sx + 16 * 64;          // [16][128]

    const int t = threadIdx.x;

    for (int idx = t; idx < 64 * 128; idx += 256) sWx[idx] = Wx[idx];
    for (int idx = t; idx < 256 * 128; idx += 256) {
        int i = idx >> 7, j = idx & 127;
        sWihT[j * 260 + i] = Wih[idx];
    }
    if (t < 128) sbx[t] = bx[t];
    sbU[t] = bih[t & 255] + bhh[t & 255];
    if (t + 0 < 256) sbU[t] = bih[t] + bhh[t];
    __syncthreads();

    const int rg = t >> 6;          // 0..3 -> rows rg*4 + q
    const int jj = t & 63;          // phase1 col pair {jj, jj+64}
    const int ii = jj * 4;          // phase2: 4 consecutive outputs
    const int ntiles = (S_LEN * B_SZ) / 16;

    for (int tile = blockIdx.x; tile < ntiles; tile += gridDim.x) {
        const int row0 = tile * 16;
        { // load 16x64 x tile (contiguous 4KB)
            const float4* src = (const float4*)(x + (size_t)row0 * XDIM);
            ((float4*)sx)[t] = src[t];
        }
        __syncthreads();

        // phase 1: feat
        float a0[4], a1[4];
        #pragma unroll
        for (int q = 0; q < 4; q++) { a0[q] = 0.f; a1[q] = 0.f; }
        #pragma unroll 8
        for (int k = 0; k < 64; k++) {
            float w0 = sWx[k * 128 + jj];
            float w1 = sWx[k * 128 + jj + 64];
            #pragma unroll
            for (int q = 0; q < 4; q++) {
                float xv = sx[(rg * 4 + q) * 64 + k];
                a0[q] = fmaf(xv, w0, a0[q]);
                a1[q] = fmaf(xv, w1, a1[q]);
            }
        }
        #pragma unroll
        for (int q = 0; q < 4; q++) {
            sfeat[(rg * 4 + q) * 128 + jj]      = tanhf(a0[q] + sbx[jj]);
            sfeat[(rg * 4 + q) * 128 + jj + 64] = tanhf(a1[q] + sbx[jj + 64]);
        }
        __syncthreads();

        // phase 2: U = feat @ Wih^T + bias
        float4 acc[4];
        #pragma unroll
        for (int q = 0; q < 4; q++) acc[q] = make_float4(0.f, 0.f, 0.f, 0.f);
        #pragma unroll 4
        for (int j = 0; j < 128; j++) {
            float4 w = *(const float4*)&sWihT[j * 260 + ii];
            #pragma unroll
            for (int q = 0; q < 4; q++) {
                float f = sfeat[(rg * 4 + q) * 128 + j];
                acc[q].x = fmaf(f, w.x, acc[q].x);
                acc[q].y = fmaf(f, w.y, acc[q].y);
                acc[q].z = fmaf(f, w.z, acc[q].z);
                acc[q].w = fmaf(f, w.w, acc[q].w);
            }
        }
        float4 bU = *(const float4*)&sbU[ii];
        #pragma unroll
        for (int q = 0; q < 4; q++) {
            float4 o;
            o.x = acc[q].x + bU.x; o.y = acc[q].y + bU.y;
            o.z = acc[q].z + bU.z; o.w = acc[q].w + bU.w;
            *((float4*)&g_U[(size_t)(row0 + rg * 4 + q) * HDIM + ii]) = o;
        }
        // no trailing sync needed: next-tile sx write is fenced by sync after
        // phase2 can't race phase1 (all threads passed the mid sync).
        __syncthreads();
    }
}

// ---------------------------------------------------------------------------
// Kernel B: sequential recurrence. One CTA per batch element (64 CTAs).
// Whh row i split: k in [0,128) in thread-i registers, k in [128,256) in smem
// (transpose-free [i][kk] layout, row stride 132 floats -> conflict-free
// LDS.128). h double-buffered in smem; one __syncthreads per step.
// ---------------------------------------------------------------------------
__global__ __launch_bounds__(256, 1) void kB(
    const float* __restrict__ Whh,
    const float* __restrict__ sigmas)
{
    extern __shared__ float sm[];
    float* sW2 = sm;               // [256][132] : Whh[i][128+kk]
    float* sh  = sW2 + 256 * 132;  // [2][256] double-buffered hidden state

    const int tid = threadIdx.x;   // output index i
    const int b   = blockIdx.x;    // batch element

    for (int idx = tid; idx < 256 * 128; idx += 256) {
        int i = idx >> 7, kk = idx & 127;
        sW2[i * 132 + kk] = Whh[i * 256 + 128 + kk];
    }

    float wr[128];
    {
        const float4* wrow = (const float4*)(Whh + tid * 256);
        #pragma unroll
        for (int k4 = 0; k4 < 32; k4++) {
            float4 w = wrow[k4];
            wr[k4 * 4 + 0] = w.x; wr[k4 * 4 + 1] = w.y;
            wr[k4 * 4 + 2] = w.z; wr[k4 * 4 + 3] = w.w;
        }
    }

    const float alpha = 1.0f / (1.0f + expf(-sigmas[tid & 3]));
    const float oma   = 1.0f - alpha;

    sh[tid] = 0.f;
    sh[256 + tid] = 0.f;
    __syncthreads();

    float u_next = g_U[(size_t)(0 * B_SZ + b) * HDIM + tid];
    int cur = 0;

    for (int t = 0; t < S_LEN; t++) {
        float u = u_next;
        if (t + 1 < S_LEN)
            u_next = g_U[(size_t)((t + 1) * B_SZ + b) * HDIM + tid];

        const float* hc = sh + cur * 256;
        float h_old = hc[tid];
        g_Hs[(size_t)(t * B_SZ + b) * HDIM + tid] = h_old;  // state entering step t

        float a0 = u, a1 = 0.f, a2 = 0.f, a3 = 0.f;
        #pragma unroll
        for (int k4 = 0; k4 < 32; k4++) {
            float4 hv = *(const float4*)&hc[k4 * 4];
            a0 = fmaf(wr[k4 * 4 + 0], hv.x, a0);
            a1 = fmaf(wr[k4 * 4 + 1], hv.y, a1);
            a2 = fmaf(wr[k4 * 4 + 2], hv.z, a2);
            a3 = fmaf(wr[k4 * 4 + 3], hv.w, a3);
        }
        const float* w2 = sW2 + tid * 132;
        #pragma unroll
        for (int k4 = 0; k4 < 32; k4++) {
            float4 hv = *(const float4*)&hc[128 + k4 * 4];
            float4 wv = *(const float4*)&w2[k4 * 4];
            a0 = fmaf(wv.x, hv.x, a0);
            a1 = fmaf(wv.y, hv.y, a1);
            a2 = fmaf(wv.z, hv.z, a2);
            a3 = fmaf(wv.w, hv.w, a3);
        }
        float h_new = tanhf((a0 + a1) + (a2 + a3));
        float h_nxt = oma * h_old + alpha * h_new;   // same form as reference

        sh[(cur ^ 1) * 256 + tid] = h_nxt;
        cur ^= 1;
        __syncthreads();
    }
}

// ---------------------------------------------------------------------------
// Kernel C: output head over all stored states (parallel):
//   z = tanh(h @ Whx + bhx) ; y = z @ Wout + bout
// ---------------------------------------------------------------------------
__global__ __launch_bounds__(256, 1) void kC(
    const float* __restrict__ Whx, const float* __restrict__ bhx,
    const float* __restrict__ Wout, const float* __restrict__ bout,
    float* __restrict__ y)
{
    extern __shared__ float sm[];
    float* sWhx  = sm;                   // [256][128] direct copy
    float* sWout = sWhx + 256 * 128;     // [128][64]  direct copy
    float* sbhx  = sWout + 128 * 64;     // [128]
    float* sbout = sbhx + 128;           // [64]
    float* sht   = sbout + 64;           // [16][256]
    float* sz    = sht + 16 * 256;       // [16][128]

    const int t = threadIdx.x;
    for (int idx = t; idx < 256 * 128; idx += 256) sWhx[idx] = Whx[idx];
    for (int idx = t; idx < 128 * 64; idx += 256) sWout[idx] = Wout[idx];
    if (t < 128) sbhx[t] = bhx[t];
    if (t < 64)  sbout[t] = bout[t];
    __syncthreads();

    const int rg  = t >> 5;          // 0..7 -> rows rg*2 + q
    const int jj4 = (t & 31) * 4;    // phase1: 4 consecutive z cols
    const int rr  = t >> 4;          // 0..15 -> row
    const int oo4 = (t & 15) * 4;    // phase2: 4 consecutive outputs
    const int ntiles = (S_LEN * B_SZ) / 16;

    for (int tile = blockIdx.x; tile < ntiles; tile += gridDim.x) {
        const int row0 = tile * 16;
        { // load 16x256 hidden-state tile (contiguous 16KB)
            const float4* src = (const float4*)(g_Hs + (size_t)row0 * HDIM);
            float4* dst = (float4*)sht;
            #pragma unroll
            for (int q = 0; q < 4; q++) dst[q * 256 + t] = src[q * 256 + t];
        }
        __syncthreads();

        // phase 1: z = tanh(h @ Whx + bhx)
        float4 acc[2];
        acc[0] = make_float4(0.f, 0.f, 0.f, 0.f);
        acc[1] = make_float4(0.f, 0.f, 0.f, 0.f);
        #pragma unroll 4
        for (int i = 0; i < 256; i++) {
            float4 w = *(const float4*)&sWhx[i * 128 + jj4];
            #pragma unroll
            for (int q = 0; q < 2; q++) {
                float h = sht[(rg * 2 + q) * 256 + i];
                acc[q].x = fmaf(h, w.x, acc[q].x);
                acc[q].y = fmaf(h, w.y, acc[q].y);
                acc[q].z = fmaf(h, w.z, acc[q].z);
                acc[q].w = fmaf(h, w.w, acc[q].w);
            }
        }
        float4 bz = *(const float4*)&sbhx[jj4];
        #pragma unroll
        for (int q = 0; q < 2; q++) {
            int r = rg * 2 + q;
            sz[r * 128 + jj4 + 0] = tanhf(acc[q].x + bz.x);
            sz[r * 128 + jj4 + 1] = tanhf(acc[q].y + bz.y);
            sz[r * 128 + jj4 + 2] = tanhf(acc[q].z + bz.z);
            sz[r * 128 + jj4 + 3] = tanhf(acc[q].w + bz.w);
        }
        __syncthreads();

        // phase 2: y = z @ Wout + bout
        float4 o = make_float4(0.f, 0.f, 0.f, 0.f);
        #pragma unroll 4
        for (int j = 0; j < 128; j++) {
            float4 w = *(const float4*)&sWout[j * 64 + oo4];
            float z = sz[rr * 128 + j];
            o.x = fmaf(z, w.x, o.x);
            o.y = fmaf(z, w.y, o.y);
            o.z = fmaf(z, w.z, o.z);
            o.w = fmaf(z, w.w, o.w);
        }
        float4 bo = *(const float4*)&sbout[oo4];
        o.x += bo.x; o.y += bo.y; o.z += bo.z; o.w += bo.w;
        *((float4*)&y[(size_t)(row0 + rr) * ODIM + oo4]) = o;
        __syncthreads();  // protect sht/sz against next-tile overwrite
    }
}

// ---------------------------------------------------------------------------
extern "C" void kernel_launch(void* const* d_in, const int* in_sizes, int n_in,
                              void* d_out, int out_size)
{
    const float* x      = (const float*)d_in[0];
    const float* Wx     = (const float*)d_in[1];
    const float* bx     = (const float*)d_in[2];
    const float* Wih    = (const float*)d_in[3];
    const float* bih    = (const float*)d_in[4];
    const float* Whh    = (const float*)d_in[5];
    const float* bhh    = (const float*)d_in[6];
    const float* Whx    = (const float*)d_in[7];
    const float* bhx    = (const float*)d_in[8];
    const float* Wout   = (const float*)d_in[9];
    const float* bout   = (const float*)d_in[10];
    const float* sigmas = (const float*)d_in[11];
    float* y = (float*)d_out;

    const size_t smA = (size_t)(64*128 + 128*260 + 128 + 256 + 16*64 + 16*128) * 4;
    const size_t smB = (size_t)(256*132 + 2*256) * 4;
    const size_t smC = (size_t)(256*128 + 128*64 + 128 + 64 + 16*256 + 16*128) * 4;

    cudaFuncSetAttribute(kA, cudaFuncAttributeMaxDynamicSharedMemorySize, (int)smA);
    cudaFuncSetAttribute(kB, cudaFuncAttributeMaxDynamicSharedMemorySize, (int)smB);
    cudaFuncSetAttribute(kC, cudaFuncAttributeMaxDynamicSharedMemorySize, (int)smC);

    kA<<<148, 256, smA>>>(x, Wx, bx, Wih, bih, bhh);
    kB<<<64, 256, smB>>>(Whh, sigmas);
    kC<<<148, 256, smC>>>(Whx, bhx, Wout, bout, y);
}

// round 2
// speedup vs baseline: 1.2313x; 1.2313x over previous
#include <cuda_runtime.h>
#include <math.h>
#include <stdint.h>

#define S_LEN 2048
#define B_SZ  64
#define XDIM  64
#define DXD   128
#define HDIM  256
#define DHD   128
#define ODIM  64

// Scratch (alloc-free rule: __device__ globals)
__device__ float g_U[S_LEN * B_SZ * HDIM];   // U[t,b,:] = feat @ Wih^T + bih + bhh
__device__ float g_Hs[S_LEN * B_SZ * HDIM];  // hidden state ENTERING step t (h_0 = 0)

// ------------------------- packed fp32x2 helpers ---------------------------
__device__ __forceinline__ unsigned long long fma2(unsigned long long a,
                                                   unsigned long long b,
                                                   unsigned long long c) {
    unsigned long long d;
    asm("fma.rn.f32x2 %0, %1, %2, %3;" : "=l"(d) : "l"(a), "l"(b), "l"(c));
    return d;
}
__device__ __forceinline__ unsigned long long add2(unsigned long long a,
                                                   unsigned long long b) {
    unsigned long long d;
    asm("add.rn.f32x2 %0, %1, %2;" : "=l"(d) : "l"(a), "l"(b));
    return d;
}
__device__ __forceinline__ float pk_lo(unsigned long long v) {
    return __uint_as_float((unsigned)(v & 0xffffffffull));
}
__device__ __forceinline__ float pk_hi(unsigned long long v) {
    return __uint_as_float((unsigned)(v >> 32));
}

__device__ __forceinline__ uint32_t smem_u32(const void* p) {
    uint32_t a;
    asm("{ .reg .u64 t; cvta.to.shared.u64 t, %1; cvt.u32.u64 %0, t; }"
        : "=r"(a) : "l"(p));
    return a;
}
__device__ __forceinline__ uint32_t ctarank() {
    uint32_t r;
    asm("mov.u32 %0, %%cluster_ctarank;" : "=r"(r));
    return r;
}
__device__ __forceinline__ void st_peer_f32(uint32_t local_addr, uint32_t peer, float v) {
    asm volatile(
        "{\n\t.reg .b32 ra;\n\t"
        "mapa.shared::cluster.u32 ra, %0, %1;\n\t"
        "st.shared::cluster.f32 [ra], %2;\n\t}"
        :: "r"(local_addr), "r"(peer), "f"(v) : "memory");
}
__device__ __forceinline__ void mbar_arrive_peer(uint32_t local_addr, uint32_t peer) {
    asm volatile(
        "{\n\t.reg .b32 ra;\n\t"
        "mapa.shared::cluster.u32 ra, %0, %1;\n\t"
        "mbarrier.arrive.release.cluster.shared::cluster.b64 _, [ra];\n\t}"
        :: "r"(local_addr), "r"(peer) : "memory");
}
__device__ __forceinline__ void mbar_wait_cluster(uint32_t addr, uint32_t parity) {
    asm volatile(
        "{\n\t.reg .pred P;\n\t"
        "W_%=:\n\t"
        "mbarrier.try_wait.parity.acquire.cluster.shared::cta.b64 P, [%0], %1, 0x989680;\n\t"
        "@!P bra W_%=;\n\t}"
        :: "r"(addr), "r"(parity) : "memory");
}

// ---------------------------------------------------------------------------
// Kernel A: fused feature extractor + input projection
//   feat = tanh(x @ Wx + bx)            [rows, 128]
//   U    = feat @ Wih^T + (bih + bhh)   [rows, 256]
// ---------------------------------------------------------------------------
__global__ __launch_bounds__(256, 1) void kA(
    const float* __restrict__ x,
    const float* __restrict__ Wx, const float* __restrict__ bx,
    const float* __restrict__ Wih, const float* __restrict__ bih,
    const float* __restrict__ bhh)
{
    extern __shared__ float sm[];
    float* sWx   = sm;                    // [64][128]
    float* sWihT = sWx + 64 * 128;        // [128][260]
    float* sbx   = sWihT + 128 * 260;     // [128]
    float* sbU   = sbx + 128;             // [256]
    float* sx    = sbU + 256;             // [16][64]
    float* sfeat = sx + 16 * 64;          // [16][128]

    const int t = threadIdx.x;

    for (int idx = t; idx < 64 * 128; idx += 256) sWx[idx] = Wx[idx];
    for (int idx = t; idx < 256 * 128; idx += 256) {
        int i = idx >> 7, j = idx & 127;
        sWihT[j * 260 + i] = Wih[idx];
    }
    if (t < 128) sbx[t] = bx[t];
    sbU[t] = bih[t] + bhh[t];
    __syncthreads();

    const int rg = t >> 6;
    const int jj = t & 63;
    const int ii = jj * 4;
    const int ntiles = (S_LEN * B_SZ) / 16;

    for (int tile = blockIdx.x; tile < ntiles; tile += gridDim.x) {
        const int row0 = tile * 16;
        {
            const float4* src = (const float4*)(x + (size_t)row0 * XDIM);
            ((float4*)sx)[t] = src[t];
        }
        __syncthreads();

        float a0[4], a1[4];
        #pragma unroll
        for (int q = 0; q < 4; q++) { a0[q] = 0.f; a1[q] = 0.f; }
        #pragma unroll 8
        for (int k = 0; k < 64; k++) {
            float w0 = sWx[k * 128 + jj];
            float w1 = sWx[k * 128 + jj + 64];
            #pragma unroll
            for (int q = 0; q < 4; q++) {
                float xv = sx[(rg * 4 + q) * 64 + k];
                a0[q] = fmaf(xv, w0, a0[q]);
                a1[q] = fmaf(xv, w1, a1[q]);
            }
        }
        #pragma unroll
        for (int q = 0; q < 4; q++) {
            sfeat[(rg * 4 + q) * 128 + jj]      = tanhf(a0[q] + sbx[jj]);
            sfeat[(rg * 4 + q) * 128 + jj + 64] = tanhf(a1[q] + sbx[jj + 64]);
        }
        __syncthreads();

        float4 acc[4];
        #pragma unroll
        for (int q = 0; q < 4; q++) acc[q] = make_float4(0.f, 0.f, 0.f, 0.f);
        #pragma unroll 4
        for (int j = 0; j < 128; j++) {
            float4 w = *(const float4*)&sWihT[j * 260 + ii];
            #pragma unroll
            for (int q = 0; q < 4; q++) {
                float f = sfeat[(rg * 4 + q) * 128 + j];
                acc[q].x = fmaf(f, w.x, acc[q].x);
                acc[q].y = fmaf(f, w.y, acc[q].y);
                acc[q].z = fmaf(f, w.z, acc[q].z);
                acc[q].w = fmaf(f, w.w, acc[q].w);
            }
        }
        float4 bU = *(const float4*)&sbU[ii];
        #pragma unroll
        for (int q = 0; q < 4; q++) {
            float4 o;
            o.x = acc[q].x + bU.x; o.y = acc[q].y + bU.y;
            o.z = acc[q].z + bU.z; o.w = acc[q].w + bU.w;
            *((float4*)&g_U[(size_t)(row0 + rg * 4 + q) * HDIM + ii]) = o;
        }
        __syncthreads();
    }
}

// ---------------------------------------------------------------------------
// Kernel B v2: sequential recurrence, 2-CTA cluster per batch element.
// CTA rank r owns K-half [128r, 128r+128) of Whh for ALL 256 outputs:
// thread j keeps W[j][half] entirely in registers (64 packed f32x2 pairs).
// Per step: 64 FFMA2 + 32 broadcast LDS.128, partials exchanged via a single
// 4B DSMEM store per thread + one mbarrier handshake. Both CTAs redundantly
// finalize all 256 outputs; h lives in registers (thread j owns h[j]).
// ---------------------------------------------------------------------------
__global__ __launch_bounds__(256, 1) __cluster_dims__(2, 1, 1)
void kB(const float* __restrict__ Whh, const float* __restrict__ sigmas)
{
    __shared__ __align__(16) float sh[128];        // own K-half of h
    __shared__ __align__(16) float spart[2][256];  // peer partials, double buffered
    __shared__ __align__(8)  unsigned long long smbar;

    const int tid = threadIdx.x;          // output index j
    const uint32_t rank = ctarank();      // 0 or 1
    const uint32_t peer = rank ^ 1u;
    const int b = blockIdx.x >> 1;        // batch element

    // Load my weight half into registers: W[tid][128*rank + kk], kk in [0,128)
    ulonglong2 wreg[32];
    {
        const ulonglong2* wsrc =
            (const ulonglong2*)(Whh + (size_t)tid * HDIM + 128 * (int)rank);
        #pragma unroll
        for (int i = 0; i < 32; i++) wreg[i] = wsrc[i];
    }

    const float alpha = 1.0f / (1.0f + expf(-sigmas[tid & 3]));
    const float oma   = 1.0f - alpha;

    if (tid < 128) sh[tid] = 0.f;
    const uint32_t mbar_a  = smem_u32(&smbar);
    const uint32_t spart_a = smem_u32(&spart[0][0]);
    if (tid == 0) {
        asm volatile("mbarrier.init.shared.b64 [%0], 1;" :: "r"(mbar_a) : "memory");
    }
    __syncthreads();
    // both CTAs' barriers + sh must be live before any remote traffic
    asm volatile("barrier.cluster.arrive.aligned;" ::: "memory");
    asm volatile("barrier.cluster.wait.aligned;" ::: "memory");

    float h_reg  = 0.f;
    float u_next = g_U[(size_t)b * HDIM + tid];
    const bool own_half = ((tid >> 7) == (int)rank);

    for (int t = 0; t < S_LEN; t++) {
        const float u = u_next;
        if (t + 1 < S_LEN)
            u_next = g_U[((size_t)(t + 1) * B_SZ + b) * HDIM + tid];

        // record state entering step t (each CTA stores its own half)
        if (own_half)
            g_Hs[((size_t)t * B_SZ + b) * HDIM + tid] = h_reg;

        // partial = sum_{kk} W[tid][half+kk] * h[half+kk]  (packed f32x2)
        unsigned long long a0 = 0ull, a1 = 0ull, a2 = 0ull, a3 = 0ull;
        #pragma unroll
        for (int i = 0; i < 32; i += 2) {
            ulonglong2 h0 = *(const ulonglong2*)&sh[i * 4];
            a0 = fma2(wreg[i].x, h0.x, a0);
            a1 = fma2(wreg[i].y, h0.y, a1);
            ulonglong2 h1 = *(const ulonglong2*)&sh[i * 4 + 4];
            a2 = fma2(wreg[i + 1].x, h1.x, a2);
            a3 = fma2(wreg[i + 1].y, h1.y, a3);
        }
        unsigned long long c = add2(add2(a0, a1), add2(a2, a3));
        const float partial = pk_lo(c) + pk_hi(c);

        // ship my partial for output tid to the peer CTA
        const int pb = t & 1;
        st_peer_f32(spart_a + (uint32_t)((pb * 256 + tid) * 4), peer, partial);
        __syncthreads();
        if (tid == 0) {
            asm volatile("fence.acq_rel.cluster;" ::: "memory");
            mbar_arrive_peer(mbar_a, peer);
        }
        mbar_wait_cluster(mbar_a, (uint32_t)pb);

        // finalize output tid (redundantly in both CTAs)
        const float s  = partial + spart[pb][tid] + u;
        const float hn = tanhf(s);
        h_reg = oma * h_reg + alpha * hn;

        if (own_half) sh[tid & 127] = h_reg;
        __syncthreads();
    }

    asm volatile("barrier.cluster.arrive.aligned;" ::: "memory");
    asm volatile("barrier.cluster.wait.aligned;" ::: "memory");
}

// ---------------------------------------------------------------------------
// Kernel C: output head over all stored states (parallel):
//   z = tanh(h @ Whx + bhx) ; y = z @ Wout + bout
// ---------------------------------------------------------------------------
__global__ __launch_bounds__(256, 1) void kC(
    const float* __restrict__ Whx, const float* __restrict__ bhx,
    const float* __restrict__ Wout, const float* __restrict__ bout,
    float* __restrict__ y)
{
    extern __shared__ float sm[];
    float* sWhx  = sm;                   // [256][128]
    float* sWout = sWhx + 256 * 128;     // [128][64]
    float* sbhx  = sWout + 128 * 64;     // [128]
    float* sbout = sbhx + 128;           // [64]
    float* sht   = sbout + 64;           // [16][256]
    float* sz    = sht + 16 * 256;       // [16][128]

    const int t = threadIdx.x;
    for (int idx = t; idx < 256 * 128; idx += 256) sWhx[idx] = Whx[idx];
    for (int idx = t; idx < 128 * 64; idx += 256) sWout[idx] = Wout[idx];
    if (t < 128) sbhx[t] = bhx[t];
    if (t < 64)  sbout[t] = bout[t];
    __syncthreads();

    const int rg  = t >> 5;
    const int jj4 = (t & 31) * 4;
    const int rr  = t >> 4;
    const int oo4 = (t & 15) * 4;
    const int ntiles = (S_LEN * B_SZ) / 16;

    for (int tile = blockIdx.x; tile < ntiles; tile += gridDim.x) {
        const int row0 = tile * 16;
        {
            const float4* src = (const float4*)(g_Hs + (size_t)row0 * HDIM);
            float4* dst = (float4*)sht;
            #pragma unroll
            for (int q = 0; q < 4; q++) dst[q * 256 + t] = src[q * 256 + t];
        }
        __syncthreads();

        float4 acc[2];
        acc[0] = make_float4(0.f, 0.f, 0.f, 0.f);
        acc[1] = make_float4(0.f, 0.f, 0.f, 0.f);
        #pragma unroll 4
        for (int i = 0; i < 256; i++) {
            float4 w = *(const float4*)&sWhx[i * 128 + jj4];
            #pragma unroll
            for (int q = 0; q < 2; q++) {
                float h = sht[(rg * 2 + q) * 256 + i];
                acc[q].x = fmaf(h, w.x, acc[q].x);
                acc[q].y = fmaf(h, w.y, acc[q].y);
                acc[q].z = fmaf(h, w.z, acc[q].z);
                acc[q].w = fmaf(h, w.w, acc[q].w);
            }
        }
        float4 bz = *(const float4*)&sbhx[jj4];
        #pragma unroll
        for (int q = 0; q < 2; q++) {
            int r = rg * 2 + q;
            sz[r * 128 + jj4 + 0] = tanhf(acc[q].x + bz.x);
            sz[r * 128 + jj4 + 1] = tanhf(acc[q].y + bz.y);
            sz[r * 128 + jj4 + 2] = tanhf(acc[q].z + bz.z);
            sz[r * 128 + jj4 + 3] = tanhf(acc[q].w + bz.w);
        }
        __syncthreads();

        float4 o = make_float4(0.f, 0.f, 0.f, 0.f);
        #pragma unroll 4
        for (int j = 0; j < 128; j++) {
            float4 w = *(const float4*)&sWout[j * 64 + oo4];
            float z = sz[rr * 128 + j];
            o.x = fmaf(z, w.x, o.x);
            o.y = fmaf(z, w.y, o.y);
            o.z = fmaf(z, w.z, o.z);
            o.w = fmaf(z, w.w, o.w);
        }
        float4 bo = *(const float4*)&sbout[oo4];
        o.x += bo.x; o.y += bo.y; o.z += bo.z; o.w += bo.w;
        *((float4*)&y[(size_t)(row0 + rr) * ODIM + oo4]) = o;
        __syncthreads();
    }
}

// ---------------------------------------------------------------------------
extern "C" void kernel_launch(void* const* d_in, const int* in_sizes, int n_in,
                              void* d_out, int out_size)
{
    const float* x      = (const float*)d_in[0];
    const float* Wx     = (const float*)d_in[1];
    const float* bx     = (const float*)d_in[2];
    const float* Wih    = (const float*)d_in[3];
    const float* bih    = (const float*)d_in[4];
    const float* Whh    = (const float*)d_in[5];
    const float* bhh    = (const float*)d_in[6];
    const float* Whx    = (const float*)d_in[7];
    const float* bhx    = (const float*)d_in[8];
    const float* Wout   = (const float*)d_in[9];
    const float* bout   = (const float*)d_in[10];
    const float* sigmas = (const float*)d_in[11];
    float* y = (float*)d_out;

    const size_t smA = (size_t)(64*128 + 128*260 + 128 + 256 + 16*64 + 16*128) * 4;
    const size_t smC = (size_t)(256*128 + 128*64 + 128 + 64 + 16*256 + 16*128) * 4;

    cudaFuncSetAttribute(kA, cudaFuncAttributeMaxDynamicSharedMemorySize, (int)smA);
    cudaFuncSetAttribute(kC, cudaFuncAttributeMaxDynamicSharedMemorySize, (int)smC);

    kA<<<148, 256, smA>>>(x, Wx, bx, Wih, bih, bhh);
    kB<<<128, 256>>>(Whh, sigmas);
    kC<<<148, 256, smC>>>(Whx, bhx, Wout, bout, y);
}

// round 4
// speedup vs baseline: 1.5603x; 1.2672x over previous
#include <cuda_runtime.h>
#include <math.h>
#include <stdint.h>

#define S_LEN 2048
#define B_SZ  64
#define XDIM  64
#define HDIM  256
#define ODIM  64

// Scratch (alloc-free rule: __device__ globals)
__device__ float g_U[S_LEN * B_SZ * HDIM];   // U[t,b,:] = feat @ Wih^T + bih + bhh
__device__ float g_Hs[S_LEN * B_SZ * HDIM];  // hidden state ENTERING step t (h_0 = 0)

// ------------------------- packed fp32x2 helpers ---------------------------
__device__ __forceinline__ unsigned long long fma2(unsigned long long a,
                                                   unsigned long long b,
                                                   unsigned long long c) {
    unsigned long long d;
    asm("fma.rn.f32x2 %0, %1, %2, %3;" : "=l"(d) : "l"(a), "l"(b), "l"(c));
    return d;
}
__device__ __forceinline__ unsigned long long add2(unsigned long long a,
                                                   unsigned long long b) {
    unsigned long long d;
    asm("add.rn.f32x2 %0, %1, %2;" : "=l"(d) : "l"(a), "l"(b));
    return d;
}
__device__ __forceinline__ float pk_lo(unsigned long long v) {
    return __uint_as_float((unsigned)(v & 0xffffffffull));
}
__device__ __forceinline__ float pk_hi(unsigned long long v) {
    return __uint_as_float((unsigned)(v >> 32));
}
// splat one fp32 into both lanes of a packed f32x2
__device__ __forceinline__ unsigned long long pk2(float v) {
    unsigned long long d;
    unsigned u = __float_as_uint(v);
    asm("mov.b64 %0, {%1, %2};" : "=l"(d) : "r"(u), "r"(u));
    return d;
}

__device__ __forceinline__ uint32_t smem_u32(const void* p) {
    uint32_t a;
    asm("{ .reg .u64 t; cvta.to.shared.u64 t, %1; cvt.u32.u64 %0, t; }"
        : "=r"(a) : "l"(p));
    return a;
}
__device__ __forceinline__ uint32_t ctarank() {
    uint32_t r;
    asm("mov.u32 %0, %%cluster_ctarank;" : "=r"(r));
    return r;
}
// remote async store with mbarrier transaction completion (no fence needed)
__device__ __forceinline__ void st_async_peer_f32(uint32_t daddr, uint32_t mbaddr,
                                                  uint32_t peer, float v) {
    asm volatile(
        "{\n\t.reg .b32 ra, rb;\n\t"
        "mapa.shared::cluster.u32 ra, %0, %2;\n\t"
        "mapa.shared::cluster.u32 rb, %1, %2;\n\t"
        "st.async.shared::cluster.mbarrier::complete_tx::bytes.f32 [ra], %3, [rb];\n\t}"
        :: "r"(daddr), "r"(mbaddr), "r"(peer), "f"(v) : "memory");
}
__device__ __forceinline__ void mbar_init(uint32_t addr, uint32_t cnt) {
    asm volatile("mbarrier.init.shared.b64 [%0], %1;" :: "r"(addr), "r"(cnt) : "memory");
}
__device__ __forceinline__ void mbar_expect_tx(uint32_t addr, uint32_t bytes) {
    asm volatile("mbarrier.arrive.expect_tx.shared.b64 _, [%0], %1;"
                 :: "r"(addr), "r"(bytes) : "memory");
}
__device__ __forceinline__ void mbar_wait_cta(uint32_t addr, uint32_t parity) {
    asm volatile(
        "{\n\t.reg .pred P;\n\t"
        "W_%=:\n\t"
        "mbarrier.try_wait.parity.acquire.cta.shared::cta.b64 P, [%0], %1, 0x989680;\n\t"
        "@!P bra W_%=;\n\t}"
        :: "r"(addr), "r"(parity) : "memory");
}

// ---------------------------------------------------------------------------
// Kernel A: feat = tanh(x @ Wx + bx); U = feat @ Wih^T + (bih + bhh)
// Phase 2 uses packed f32x2 FMAs + float4 activation loads.
// ---------------------------------------------------------------------------
__global__ __launch_bounds__(256, 1) void kA(
    const float* __restrict__ x,
    const float* __restrict__ Wx, const float* __restrict__ bx,
    const float* __restrict__ Wih, const float* __restrict__ bih,
    const float* __restrict__ bhh)
{
    extern __shared__ float sm[];
    float* sWx   = sm;                    // [64][128]
    float* sWihT = sWx + 64 * 128;        // [128][260]
    float* sbx   = sWihT + 128 * 260;     // [128]
    float* sbU   = sbx + 128;             // [256]
    float* sx    = sbU + 256;             // [16][64]
    float* sfeat = sx + 16 * 64;          // [16][128]

    const int t = threadIdx.x;

    for (int idx = t; idx < 64 * 128; idx += 256) sWx[idx] = Wx[idx];
    for (int idx = t; idx < 256 * 128; idx += 256) {
        int i = idx >> 7, j = idx & 127;
        sWihT[j * 260 + i] = Wih[idx];
    }
    if (t < 128) sbx[t] = bx[t];
    sbU[t] = bih[t] + bhh[t];
    __syncthreads();

    const int rg = t >> 6;
    const int jj = t & 63;
    const int ii = jj * 4;
    const int ntiles = (S_LEN * B_SZ) / 16;

    for (int tile = blockIdx.x; tile < ntiles; tile += gridDim.x) {
        const int row0 = tile * 16;
        {
            const float4* src = (const float4*)(x + (size_t)row0 * XDIM);
            ((float4*)sx)[t] = src[t];
        }
        __syncthreads();

        // phase 1: feat = tanh(x @ Wx + bx)
        float a0[4], a1[4];
        #pragma unroll
        for (int q = 0; q < 4; q++) { a0[q] = 0.f; a1[q] = 0.f; }
        #pragma unroll 8
        for (int k = 0; k < 64; k++) {
            float w0 = sWx[k * 128 + jj];
            float w1 = sWx[k * 128 + jj + 64];
            #pragma unroll
            for (int q = 0; q < 4; q++) {
                float xv = sx[(rg * 4 + q) * 64 + k];
                a0[q] = fmaf(xv, w0, a0[q]);
                a1[q] = fmaf(xv, w1, a1[q]);
            }
        }
        #pragma unroll
        for (int q = 0; q < 4; q++) {
            sfeat[(rg * 4 + q) * 128 + jj]      = tanhf(a0[q] + sbx[jj]);
            sfeat[(rg * 4 + q) * 128 + jj + 64] = tanhf(a1[q] + sbx[jj + 64]);
        }
        __syncthreads();

        // phase 2: U = feat @ Wih^T + bias   (packed f32x2)
        unsigned long long acc01[4], acc23[4];
        #pragma unroll
        for (int q = 0; q < 4; q++) { acc01[q] = 0ull; acc23[q] = 0ull; }
        #pragma unroll 2
        for (int j4 = 0; j4 < 128; j4 += 4) {
            float f[4][4];
            #pragma unroll
            for (int q = 0; q < 4; q++)
                *(float4*)&f[q][0] = *(const float4*)&sfeat[(rg * 4 + q) * 128 + j4];
            #pragma unroll
            for (int s = 0; s < 4; s++) {
                ulonglong2 w = *(const ulonglong2*)&sWihT[(j4 + s) * 260 + ii];
                #pragma unroll
                for (int q = 0; q < 4; q++) {
                    unsigned long long fs = pk2(f[q][s]);
                    acc01[q] = fma2(fs, w.x, acc01[q]);
                    acc23[q] = fma2(fs, w.y, acc23[q]);
                }
            }
        }
        float4 bU = *(const float4*)&sbU[ii];
        #pragma unroll
        for (int q = 0; q < 4; q++) {
            float4 o;
            o.x = pk_lo(acc01[q]) + bU.x; o.y = pk_hi(acc01[q]) + bU.y;
            o.z = pk_lo(acc23[q]) + bU.z; o.w = pk_hi(acc23[q]) + bU.w;
            *((float4*)&g_U[(size_t)(row0 + rg * 4 + q) * HDIM + ii]) = o;
        }
        __syncthreads();
    }
}

// ---------------------------------------------------------------------------
// Kernel B v4: sequential recurrence, 2-CTA cluster per batch, output-split.
// Same as v3 but the h vector is DOUBLE-BUFFERED by step parity: writers at
// step t publish into sh[t&1] (local store + st.async to peer), readers at
// step t read sh[(t+1)&1]. The v3 race (peer's step-t st.async overwriting
// words still being read for step t-1) is eliminated: peer's step-(t+1) send
// to buffer A happens-after my step-t reads of buffer A via the chain
// my-reads -> my-send -> peer-unblock -> peer-send.
// ---------------------------------------------------------------------------
__global__ __launch_bounds__(256, 1) __cluster_dims__(2, 1, 1)
void kB(const float* __restrict__ Whh, const float* __restrict__ sigmas)
{
    __shared__ __align__(16) float sh[2][256];  // double-buffered h vector
    __shared__ __align__(16) float spart[128];  // intra-CTA partial exchange
    __shared__ __align__(8)  unsigned long long mbar[2];

    const int tid   = threadIdx.x;
    const int i_loc = tid & 127;
    const int half  = tid >> 7;
    const uint32_t rank = ctarank();
    const uint32_t peer = rank ^ 1u;
    const int r  = (int)rank;
    const int b  = blockIdx.x >> 1;
    const int gi = r * 128 + i_loc;          // output index this thread serves
    const bool fresh     = (half == r);      // my K-half is produced locally
    const bool finalizer = (half == 0);
    const int waiter_leader = (r == 0) ? 128 : 0;   // one mbar-waiting thread

    // weights: W[gi][128*half + kk], kk in [0,128) -> 32 ulonglong2 = 128 regs
    ulonglong2 wreg[32];
    {
        const ulonglong2* ws =
            (const ulonglong2*)(Whh + (size_t)gi * HDIM + 128 * half);
        #pragma unroll
        for (int i = 0; i < 32; i++) wreg[i] = ws[i];
    }

    const float alpha = 1.0f / (1.0f + expf(-sigmas[gi & 3]));
    const float oma   = 1.0f - alpha;

    sh[0][tid] = 0.f;
    sh[1][tid] = 0.f;
    const uint32_t mb[2] = { smem_u32(&mbar[0]), smem_u32(&mbar[1]) };
    const uint32_t sh_a  = smem_u32(&sh[0][0]);
    if (tid == 0) { mbar_init(mb[0], 1); mbar_init(mb[1], 1); }
    __syncthreads();
    if (tid == waiter_leader) {              // cover sends of steps 0 and 1
        mbar_expect_tx(mb[0], 512);
        mbar_expect_tx(mb[1], 512);
    }
    __syncthreads();
    asm volatile("barrier.cluster.arrive.aligned;" ::: "memory");
    asm volatile("barrier.cluster.wait.aligned;" ::: "memory");

    float h_reg  = 0.f;                      // finalizer-owned h[gi]
    float u_next = finalizer ? g_U[(size_t)b * HDIM + gi] : 0.f;

    for (int t = 0; t < S_LEN; t++) {
        // h entering step t lives in buffer (t-1)&1 == (t+1)&1
        const float* hsrc = sh[(t + 1) & 1] + 128 * half;

        // threads on the remote K-half wait for the peer's step-(t-1) h values
        if (!fresh && t > 0) {
            const int pm = (t - 1) & 1;
            mbar_wait_cta(mb[pm], (uint32_t)(((t - 1) >> 1) & 1));
            if (tid == waiter_leader)        // re-arm for use at step t+1
                mbar_expect_tx(mb[pm], 512);
        }

        // partial = sum_kk W[gi][128*half+kk] * h[128*half+kk]
        unsigned long long a0 = 0ull, a1 = 0ull, a2 = 0ull, a3 = 0ull;
        #pragma unroll
        for (int i = 0; i < 32; i += 2) {
            ulonglong2 h0 = *(const ulonglong2*)&hsrc[i * 4];
            a0 = fma2(wreg[i].x, h0.x, a0);
            a1 = fma2(wreg[i].y, h0.y, a1);
            ulonglong2 h1 = *(const ulonglong2*)&hsrc[i * 4 + 4];
            a2 = fma2(wreg[i + 1].x, h1.x, a2);
            a3 = fma2(wreg[i + 1].y, h1.y, a3);
        }
        unsigned long long c = add2(add2(a0, a1), add2(a2, a3));
        const float partial = pk_lo(c) + pk_hi(c);

        if (!finalizer) spart[i_loc] = partial;
        __syncthreads();

        if (finalizer) {
            const float u = u_next;
            if (t + 1 < S_LEN)
                u_next = g_U[((size_t)(t + 1) * B_SZ + b) * HDIM + gi];
            g_Hs[((size_t)t * B_SZ + b) * HDIM + gi] = h_reg;  // state entering t

            const float s  = partial + spart[i_loc] + u;
            const float hn = tanhf(s);
            h_reg = oma * h_reg + alpha * hn;

            const int wb = t & 1;
            sh[wb][gi] = h_reg;                               // local publish
            st_async_peer_f32(sh_a + (uint32_t)((wb * 256 + gi) * 4),
                              mb[wb], peer, h_reg);           // remote publish + tx
        }
        __syncthreads();
    }

    asm volatile("barrier.cluster.arrive.aligned;" ::: "memory");
    asm volatile("barrier.cluster.wait.aligned;" ::: "memory");
}

// ---------------------------------------------------------------------------
// Kernel C: z = tanh(h @ Whx + bhx); y = z @ Wout + bout
// Phase 1 uses packed f32x2 FMAs + float4 activation loads.
// ---------------------------------------------------------------------------
__global__ __launch_bounds__(256, 1) void kC(
    const float* __restrict__ Whx, const float* __restrict__ bhx,
    const float* __restrict__ Wout, const float* __restrict__ bout,
    float* __restrict__ y)
{
    extern __shared__ float sm[];
    float* sWhx  = sm;                   // [256][128]
    float* sWout = sWhx + 256 * 128;     // [128][64]
    float* sbhx  = sWout + 128 * 64;     // [128]
    float* sbout = sbhx + 128;           // [64]
    float* sht   = sbout + 64;           // [16][256]
    float* sz    = sht + 16 * 256;       // [16][128]

    const int t = threadIdx.x;
    for (int idx = t; idx < 256 * 128; idx += 256) sWhx[idx] = Whx[idx];
    for (int idx = t; idx < 128 * 64; idx += 256) sWout[idx] = Wout[idx];
    if (t < 128) sbhx[t] = bhx[t];
    if (t < 64)  sbout[t] = bout[t];
    __syncthreads();

    const int rg  = t >> 5;
    const int jj4 = (t & 31) * 4;
    const int rr  = t >> 4;
    const int oo4 = (t & 15) * 4;
    const int ntiles = (S_LEN * B_SZ) / 16;

    for (int tile = blockIdx.x; tile < ntiles; tile += gridDim.x) {
        const int row0 = tile * 16;
        {
            const float4* src = (const float4*)(g_Hs + (size_t)row0 * HDIM);
            float4* dst = (float4*)sht;
            #pragma unroll
            for (int q = 0; q < 4; q++) dst[q * 256 + t] = src[q * 256 + t];
        }
        __syncthreads();

        // phase 1: z = tanh(h @ Whx + bhx)   (packed f32x2)
        unsigned long long acc01[2], acc23[2];
        acc01[0] = acc01[1] = acc23[0] = acc23[1] = 0ull;
        #pragma unroll 2
        for (int i4 = 0; i4 < 256; i4 += 4) {
            float h[2][4];
            #pragma unroll
            for (int q = 0; q < 2; q++)
                *(float4*)&h[q][0] = *(const float4*)&sht[(rg * 2 + q) * 256 + i4];
            #pragma unroll
            for (int s = 0; s < 4; s++) {
                ulonglong2 w = *(const ulonglong2*)&sWhx[(i4 + s) * 128 + jj4];
                #pragma unroll
                for (int q = 0; q < 2; q++) {
                    unsigned long long hs = pk2(h[q][s]);
                    acc01[q] = fma2(hs, w.x, acc01[q]);
                    acc23[q] = fma2(hs, w.y, acc23[q]);
                }
            }
        }
        float4 bz = *(const float4*)&sbhx[jj4];
        #pragma unroll
        for (int q = 0; q < 2; q++) {
            int rw = rg * 2 + q;
            sz[rw * 128 + jj4 + 0] = tanhf(pk_lo(acc01[q]) + bz.x);
            sz[rw * 128 + jj4 + 1] = tanhf(pk_hi(acc01[q]) + bz.y);
            sz[rw * 128 + jj4 + 2] = tanhf(pk_lo(acc23[q]) + bz.z);
            sz[rw * 128 + jj4 + 3] = tanhf(pk_hi(acc23[q]) + bz.w);
        }
        __syncthreads();

        // phase 2: y = z @ Wout + bout
        float4 o = make_float4(0.f, 0.f, 0.f, 0.f);
        #pragma unroll 4
        for (int j = 0; j < 128; j++) {
            float4 w = *(const float4*)&sWout[j * 64 + oo4];
            float z = sz[rr * 128 + j];
            o.x = fmaf(z, w.x, o.x);
            o.y = fmaf(z, w.y, o.y);
            o.z = fmaf(z, w.z, o.z);
            o.w = fmaf(z, w.w, o.w);
        }
        float4 bo = *(const float4*)&sbout[oo4];
        o.x += bo.x; o.y += bo.y; o.z += bo.z; o.w += bo.w;
        *((float4*)&y[(size_t)(row0 + rr) * ODIM + oo4]) = o;
        __syncthreads();
    }
}

// ---------------------------------------------------------------------------
extern "C" void kernel_launch(void* const* d_in, const int* in_sizes, int n_in,
                              void* d_out, int out_size)
{
    const float* x      = (const float*)d_in[0];
    const float* Wx     = (const float*)d_in[1];
    const float* bx     = (const float*)d_in[2];
    const float* Wih    = (const float*)d_in[3];
    const float* bih    = (const float*)d_in[4];
    const float* Whh    = (const float*)d_in[5];
    const float* bhh    = (const float*)d_in[6];
    const float* Whx    = (const float*)d_in[7];
    const float* bhx    = (const float*)d_in[8];
    const float* Wout   = (const float*)d_in[9];
    const float* bout   = (const float*)d_in[10];
    const float* sigmas = (const float*)d_in[11];
    float* y = (float*)d_out;

    const size_t smA = (size_t)(64*128 + 128*260 + 128 + 256 + 16*64 + 16*128) * 4;
    const size_t smC = (size_t)(256*128 + 128*64 + 128 + 64 + 16*256 + 16*128) * 4;

    cudaFuncSetAttribute(kA, cudaFuncAttributeMaxDynamicSharedMemorySize, (int)smA);
    cudaFuncSetAttribute(kC, cudaFuncAttributeMaxDynamicSharedMemorySize, (int)smC);

    kA<<<148, 256, smA>>>(x, Wx, bx, Wih, bih, bhh);
    kB<<<128, 256>>>(Whh, sigmas);
    kC<<<148, 256, smC>>>(Whx, bhx, Wout, bout, y);
}